// round 9
// baseline (speedup 1.0000x reference)
#include <cuda_runtime.h>
#include <cstdint>

// ---------------- constants ----------------
#define B_   128
#define C_   64
#define S_   4096
#define NROW (B_*C_)            // 8192
#define NTOT ((size_t)B_*C_*S_) // 33554432

// ---------------- scratch (no allocation allowed) ----------------
__device__ float g_sd[NROW];        // sqrt2 * 0.1 * per-row std (shared by views)
__device__ int   g_shift[2*B_];
__device__ float g_scale[2*B_];
__device__ float g_mask[2*NROW];

// ---------------- Threefry-2x32-20 (JAX-exact) ----------------
#define TF_R(x0,x1,r) { x0 += x1; x1 = __funnelshift_l(x1,x1,r); x1 ^= x0; }

// plain version (prep kernel, low volume)
__device__ __forceinline__ void tf_block0(uint32_t k0, uint32_t k1,
                                          uint32_t c1,
                                          uint32_t &o0, uint32_t &o1) {
  uint32_t k2 = k0 ^ k1 ^ 0x1BD11BDAu;
  uint32_t x0 = k0, x1 = c1 + k1;
  TF_R(x0,x1,13) TF_R(x0,x1,15) TF_R(x0,x1,26) TF_R(x0,x1,6)
  x0 += k1; x1 += k2 + 1u;
  TF_R(x0,x1,17) TF_R(x0,x1,29) TF_R(x0,x1,16) TF_R(x0,x1,24)
  x0 += k2; x1 += k0 + 2u;
  TF_R(x0,x1,13) TF_R(x0,x1,15) TF_R(x0,x1,26) TF_R(x0,x1,6)
  x0 += k0; x1 += k1 + 3u;
  TF_R(x0,x1,17) TF_R(x0,x1,29) TF_R(x0,x1,16) TF_R(x0,x1,24)
  x0 += k1; x1 += k2 + 4u;
  TF_R(x0,x1,13) TF_R(x0,x1,15) TF_R(x0,x1,26) TF_R(x0,x1,6)
  o0 = x0 + k2; o1 = x1 + k0 + 5u;
}

__device__ __forceinline__ uint32_t xbits(uint32_t k0, uint32_t k1, uint32_t i) {
  uint32_t o0, o1;
  tf_block0(k0, k1, i, o0, o1);
  return o0 ^ o1;
}

// ---- hot-path block: round adds via IMAD (runtime `one`), injections merged
// into the next round's add as a 3-input add. Returns o0^o1 directly.
#define MAD1(d,a) asm("mad.lo.u32 %0, %1, %2, %0;" : "+r"(d) : "r"(a), "r"(one))
#define TF_RM(r)  { MAD1(x0,x1); x1 = __funnelshift_l(x1,x1,r); x1 ^= x0; }
// injection k into x0 merged with this round's add; i already added to x1
#define TF_INJ(ka,ib,r) { x1 += ib; x0 = x0 + ka + x1; \
                          x1 = __funnelshift_l(x1,x1,r); x1 ^= x0; }

__device__ __forceinline__ uint32_t tf_xor(uint32_t k0, uint32_t k1,
                                           uint32_t k2,
                                           uint32_t i1, uint32_t i2,
                                           uint32_t i3, uint32_t i4,
                                           uint32_t i5,
                                           uint32_t c1, uint32_t one) {
  uint32_t x0 = k0, x1 = c1 + k1;
  TF_RM(13) TF_RM(15) TF_RM(26) TF_RM(6)
  TF_INJ(k1, i1, 17) TF_RM(29) TF_RM(16) TF_RM(24)
  TF_INJ(k2, i2, 13) TF_RM(15) TF_RM(26) TF_RM(6)
  TF_INJ(k0, i3, 17) TF_RM(29) TF_RM(16) TF_RM(24)
  TF_INJ(k1, i4, 13) TF_RM(15) TF_RM(26) TF_RM(6)
  return (x0 + k2) ^ (x1 + i5);
}

// bits -> float in [0,1): JAX _uniform exact (prep path)
__device__ __forceinline__ float u01(uint32_t b) {
  return __uint_as_float((b >> 9) | 0x3F800000u) - 1.0f;
}

// erfinv(u_sym(bits)) WITHOUT sqrt(2) (folded into sd).
// Exponent-bump uniform: x = bitcast((b>>9)|2.0f-exp) - 3, then CLAMP to
// lo=-0.99999994 (bits==0 would give exactly -1 -> log(0) = -inf; the
// reference's lo exists to exclude that point). |Δx| <= 6e-8 elsewhere.
// v = lg2(1-x^2) via MUFU; w = -ln2*v folded into poly arg.
// Polys truncated 9->5 terms (output impact ~1e-5 rms vs 1e-3 budget).
__device__ __forceinline__ float erfinv_from_bits(uint32_t bts) {
  float x = __uint_as_float((bts >> 9) | 0x40000000u) - 3.0f;
  x = fmaxf(x, -0.99999994f);                   // exclude exact -1
  float v = __log2f(fmaf(-x, x, 1.0f));         // lg2(1 - x^2)  <= 0
  float p;
  if (v > -7.2134752f) {                        // w < 5
    float t = fmaf(-0.69314718f, v, -2.5f);     // w - 2.5
    p = 0.00021858087f;
    p = fmaf(p, t, -0.00125372503f);
    p = fmaf(p, t, -0.00417768164f);
    p = fmaf(p, t, 0.246640727f);
    p = fmaf(p, t, 1.50140941f);
  } else {
    float w = -0.69314718f * v;
    float t = sqrtf(w) - 3.0f;
    p = 0.00573950773f;
    p = fmaf(p, t, -0.0076224613f);
    p = fmaf(p, t, 0.00943887047f);
    p = fmaf(p, t, 1.00167406f);
    p = fmaf(p, t, 2.83297682f);
  }
  return p * x;
}

// ---------------- fused prep: per-row std + shifts/masks/scales ----------------
__global__ void prep_kernel(const float* __restrict__ x,
                            uint4 kshA, uint4 kshB, uint4 kmask, uint4 kscale) {
  unsigned gt = blockIdx.x * blockDim.x + threadIdx.x;
  if (gt < 2u * 8448u) {
    int v = (gt >= 8448u);
    unsigned i = gt - (unsigned)v * 8448u;
    if (i < 8192u) {
      uint32_t k0 = v ? kmask.z : kmask.x, k1 = v ? kmask.w : kmask.y;
      g_mask[v * NROW + i] = (u01(xbits(k0, k1, i)) > 0.1f) ? 1.0f : 0.0f;
    } else if (i < 8320u) {
      // randint: k1,k2 = split(k_shift); higher from k1, lower from k2; 68 = 2^32 % 101
      unsigned b = i - 8192u;
      uint4 ks = v ? kshB : kshA;
      uint32_t hb = xbits(ks.x, ks.y, b);
      uint32_t lb = xbits(ks.z, ks.w, b);
      uint32_t off = ((hb % 101u) * 68u + (lb % 101u)) % 101u;
      g_shift[v * B_ + b] = -50 + (int)off;
    } else {
      unsigned j = i - 8320u;
      uint32_t k0 = v ? kscale.z : kscale.x, k1 = v ? kscale.w : kscale.y;
      float u = u01(xbits(k0, k1, j));
      const float span = 1.2f - 0.8f;
      g_scale[v * B_ + j] = fmaxf(0.8f, __fadd_rn(__fmul_rn(u, span), 0.8f));
    }
  }

  int row = blockIdx.x;
  const float4* xr = reinterpret_cast<const float4*>(x + ((size_t)row << 12));
  float s = 0.0f, q = 0.0f;
#pragma unroll
  for (int i = 0; i < 8; i++) {
    float4 v = xr[threadIdx.x + (i << 7)];
    s += (v.x + v.y) + (v.z + v.w);
    q += (v.x * v.x + v.y * v.y) + (v.z * v.z + v.w * v.w);
  }
#pragma unroll
  for (int o = 16; o; o >>= 1) {
    s += __shfl_down_sync(0xFFFFFFFFu, s, o);
    q += __shfl_down_sync(0xFFFFFFFFu, q, o);
  }
  __shared__ float ss[4], qq[4];
  int w = threadIdx.x >> 5;
  if ((threadIdx.x & 31) == 0) { ss[w] = s; qq[w] = q; }
  __syncthreads();
  if (threadIdx.x == 0) {
    s = ss[0] + ss[1] + ss[2] + ss[3];
    q = qq[0] + qq[1] + qq[2] + qq[3];
    float mean = s * (1.0f / 4096.0f);
    float var = (q - 4096.0f * mean * mean) * (1.0f / 4095.0f);
    // fold 0.1 (NOISE_STD) and sqrt(2) (from normal) into one factor
    g_sd[row] = 0.141421356237f * sqrtf(fmaxf(var, 0.0f));
  }
}

// ---------------- main: 4 consecutive elements per thread, both views ----------------
__global__ void __launch_bounds__(256) main_kernel(const float* __restrict__ x,
                                                   float* __restrict__ out,
                                                   uint4 knoise, uint32_t one) {
  unsigned t0 = (blockIdx.x * blockDim.x + threadIdx.x) * 4u;  // s%4==0
  int b = t0 >> 18;
  int s0 = t0 & 4095;
  int row = t0 >> 12;
  size_t base = (size_t)row << 12;
  float sd = g_sd[row];
  int sh0 = g_shift[b];
  int sh1 = g_shift[B_ + b];
  float ms0 = g_mask[row]        * g_scale[b];
  float ms1 = g_mask[NROW + row] * g_scale[B_ + b];

  // per-key derived constants (hoisted; warp-uniform)
  uint32_t ka0 = knoise.x, ka1 = knoise.y;
  uint32_t ka2 = ka0 ^ ka1 ^ 0x1BD11BDAu;
  uint32_t a_i1 = ka2 + 1u, a_i2 = ka0 + 2u, a_i3 = ka1 + 3u,
           a_i4 = ka2 + 4u, a_i5 = ka0 + 5u;
  uint32_t kb0 = knoise.z, kb1 = knoise.w;
  uint32_t kb2 = kb0 ^ kb1 ^ 0x1BD11BDAu;
  uint32_t b_i1 = kb2 + 1u, b_i2 = kb0 + 2u, b_i3 = kb1 + 3u,
           b_i4 = kb2 + 4u, b_i5 = kb0 + 5u;

  float4 o0, o1;
  float* p0 = &o0.x;
  float* p1 = &o1.x;
#pragma unroll
  for (int j = 0; j < 4; j++) {
    uint32_t wa = tf_xor(ka0, ka1, ka2, a_i1, a_i2, a_i3, a_i4, a_i5, t0 + j, one);
    uint32_t wb = tf_xor(kb0, kb1, kb2, b_i1, b_i2, b_i3, b_i4, b_i5, t0 + j, one);
    float z0 = erfinv_from_bits(wa);
    float z1 = erfinv_from_bits(wb);
    float xv0 = __ldg(x + base + (unsigned)((s0 + j - sh0) & 4095));
    float xv1 = __ldg(x + base + (unsigned)((s0 + j - sh1) & 4095));
    p0[j] = (xv0 + z0 * sd) * ms0;
    p1[j] = (xv1 + z1 * sd) * ms1;
  }

  *reinterpret_cast<float4*>(out + base + s0)        = o0;
  *reinterpret_cast<float4*>(out + NTOT + base + s0) = o1;
}

// ---------------- host-side Threefry for constant key derivation ----------------
static inline uint32_t h_rotl(uint32_t x, int r) { return (x << r) | (x >> (32 - r)); }
static void h_tf(uint32_t k0, uint32_t k1, uint32_t x0, uint32_t x1,
                 uint32_t* o0, uint32_t* o1) {
  uint32_t k2 = k0 ^ k1 ^ 0x1BD11BDAu;
  x0 += k0; x1 += k1;
#define HR(r) { x0 += x1; x1 = h_rotl(x1, r); x1 ^= x0; }
  HR(13) HR(15) HR(26) HR(6)  x0 += k1; x1 += k2 + 1u;
  HR(17) HR(29) HR(16) HR(24) x0 += k2; x1 += k0 + 2u;
  HR(13) HR(15) HR(26) HR(6)  x0 += k0; x1 += k1 + 3u;
  HR(17) HR(29) HR(16) HR(24) x0 += k1; x1 += k2 + 4u;
  HR(13) HR(15) HR(26) HR(6)  x0 += k2; x1 += k0 + 5u;
#undef HR
  *o0 = x0; *o1 = x1;
}

extern "C" void kernel_launch(void* const* d_in, const int* in_sizes, int n_in,
                              void* d_out, int out_size) {
  const float* x = (const float*)d_in[0];
  float* out = (float*)d_out;

  uint32_t vk[2][2];
  h_tf(0u, 42u, 0u, 1u, &vk[0][0], &vk[0][1]);
  h_tf(0u, 42u, 0u, 2u, &vk[1][0], &vk[1][1]);

  uint4 kshA, kshB, knoise, kmask, kscale;
  for (int v = 0; v < 2; v++) {
    uint32_t kj[4][2];
    for (uint32_t j = 0; j < 4; j++)
      h_tf(vk[v][0], vk[v][1], 0u, j, &kj[j][0], &kj[j][1]);
    uint32_t s1[2], s2[2];
    h_tf(kj[0][0], kj[0][1], 0u, 0u, &s1[0], &s1[1]);
    h_tf(kj[0][0], kj[0][1], 0u, 1u, &s2[0], &s2[1]);
    if (v == 0) {
      kshA.x = s1[0]; kshA.y = s1[1]; kshA.z = s2[0]; kshA.w = s2[1];
      knoise.x = kj[1][0]; knoise.y = kj[1][1];
      kmask.x  = kj[2][0]; kmask.y  = kj[2][1];
      kscale.x = kj[3][0]; kscale.y = kj[3][1];
    } else {
      kshB.x = s1[0]; kshB.y = s1[1]; kshB.z = s2[0]; kshB.w = s2[1];
      knoise.z = kj[1][0]; knoise.w = kj[1][1];
      kmask.z  = kj[2][0]; kmask.w  = kj[2][1];
      kscale.z = kj[3][0]; kscale.w = kj[3][1];
    }
  }

  prep_kernel<<<NROW, 128>>>(x, kshA, kshB, kmask, kscale);
  main_kernel<<<(unsigned)(NTOT / 4 / 256), 256>>>(x, out, knoise, 1u);
}

// round 10
// speedup vs baseline: 1.0677x; 1.0677x over previous
#include <cuda_runtime.h>
#include <cstdint>

// ---------------- constants ----------------
#define B_   128
#define C_   64
#define S_   4096
#define NROW (B_*C_)            // 8192
#define NTOT ((size_t)B_*C_*S_) // 33554432

// ---------------- scratch (no allocation allowed) ----------------
__device__ float g_sd[NROW];        // sqrt2 * 0.1 * per-row std (shared by views)
__device__ int   g_shift[2*B_];
__device__ float g_scale[2*B_];
__device__ float g_mask[2*NROW];

// ---------------- Threefry-2x32-20 (JAX-exact) ----------------
#define TF_R(x0,x1,r) { x0 += x1; x1 = __funnelshift_l(x1,x1,r); x1 ^= x0; }

// plain version (prep kernel, low volume)
__device__ __forceinline__ void tf_block0(uint32_t k0, uint32_t k1,
                                          uint32_t c1,
                                          uint32_t &o0, uint32_t &o1) {
  uint32_t k2 = k0 ^ k1 ^ 0x1BD11BDAu;
  uint32_t x0 = k0, x1 = c1 + k1;
  TF_R(x0,x1,13) TF_R(x0,x1,15) TF_R(x0,x1,26) TF_R(x0,x1,6)
  x0 += k1; x1 += k2 + 1u;
  TF_R(x0,x1,17) TF_R(x0,x1,29) TF_R(x0,x1,16) TF_R(x0,x1,24)
  x0 += k2; x1 += k0 + 2u;
  TF_R(x0,x1,13) TF_R(x0,x1,15) TF_R(x0,x1,26) TF_R(x0,x1,6)
  x0 += k0; x1 += k1 + 3u;
  TF_R(x0,x1,17) TF_R(x0,x1,29) TF_R(x0,x1,16) TF_R(x0,x1,24)
  x0 += k1; x1 += k2 + 4u;
  TF_R(x0,x1,13) TF_R(x0,x1,15) TF_R(x0,x1,26) TF_R(x0,x1,6)
  o0 = x0 + k2; o1 = x1 + k0 + 5u;
}

__device__ __forceinline__ uint32_t xbits(uint32_t k0, uint32_t k1, uint32_t i) {
  uint32_t o0, o1;
  tf_block0(k0, k1, i, o0, o1);
  return o0 ^ o1;
}

// ---- hot-path block: EVERY add as IMAD (fma pipe) via runtime `one`.
// alu pipe keeps only the unavoidable SHF + LOP3 per round.
// (R7 balance — best measured: issue 86.5%. R9's IADD3 merge regressed.)
#define MAD1(d,a) asm("mad.lo.u32 %0, %1, %2, %0;" : "+r"(d) : "r"(a), "r"(one))
#define TF_RM(r)  { MAD1(x0,x1); x1 = __funnelshift_l(x1,x1,r); x1 ^= x0; }

__device__ __forceinline__ uint32_t tf_xor(uint32_t k0, uint32_t k1,
                                           uint32_t k2,
                                           uint32_t i1, uint32_t i2,
                                           uint32_t i3, uint32_t i4,
                                           uint32_t i5,
                                           uint32_t c1, uint32_t one) {
  uint32_t x0 = k0, x1 = c1;
  MAD1(x1, k1);
  TF_RM(13) TF_RM(15) TF_RM(26) TF_RM(6)
  MAD1(x0, k1); MAD1(x1, i1);
  TF_RM(17) TF_RM(29) TF_RM(16) TF_RM(24)
  MAD1(x0, k2); MAD1(x1, i2);
  TF_RM(13) TF_RM(15) TF_RM(26) TF_RM(6)
  MAD1(x0, k0); MAD1(x1, i3);
  TF_RM(17) TF_RM(29) TF_RM(16) TF_RM(24)
  MAD1(x0, k1); MAD1(x1, i4);
  TF_RM(13) TF_RM(15) TF_RM(26) TF_RM(6)
  MAD1(x0, k2); MAD1(x1, i5);
  return x0 ^ x1;
}

// bits -> float in [0,1): JAX _uniform exact (prep path)
__device__ __forceinline__ float u01(uint32_t b) {
  return __uint_as_float((b >> 9) | 0x3F800000u) - 1.0f;
}

// erfinv(u_sym(bits)) WITHOUT sqrt(2) (folded into sd).
// Exponent-bump uniform + clamp at -0.99999994 (excludes exact -1 -> -inf).
// v = lg2(1-x^2) via MUFU; w = -ln2*v folded into poly arg.
// Polys truncated 9->5 terms (output impact ~1e-5 rms vs 1e-3 budget).
__device__ __forceinline__ float erfinv_from_bits(uint32_t bts) {
  float x = __uint_as_float((bts >> 9) | 0x40000000u) - 3.0f;
  x = fmaxf(x, -0.99999994f);                   // exclude exact -1
  float v = __log2f(fmaf(-x, x, 1.0f));         // lg2(1 - x^2)  <= 0
  float p;
  if (v > -7.2134752f) {                        // w < 5
    float t = fmaf(-0.69314718f, v, -2.5f);     // w - 2.5
    p = 0.00021858087f;
    p = fmaf(p, t, -0.00125372503f);
    p = fmaf(p, t, -0.00417768164f);
    p = fmaf(p, t, 0.246640727f);
    p = fmaf(p, t, 1.50140941f);
  } else {
    float w = -0.69314718f * v;
    float t = sqrtf(w) - 3.0f;
    p = 0.00573950773f;
    p = fmaf(p, t, -0.0076224613f);
    p = fmaf(p, t, 0.00943887047f);
    p = fmaf(p, t, 1.00167406f);
    p = fmaf(p, t, 2.83297682f);
  }
  return p * x;
}

// ---------------- fused prep: per-row std + shifts/masks/scales ----------------
__global__ void prep_kernel(const float* __restrict__ x,
                            uint4 kshA, uint4 kshB, uint4 kmask, uint4 kscale) {
  unsigned gt = blockIdx.x * blockDim.x + threadIdx.x;
  if (gt < 2u * 8448u) {
    int v = (gt >= 8448u);
    unsigned i = gt - (unsigned)v * 8448u;
    if (i < 8192u) {
      uint32_t k0 = v ? kmask.z : kmask.x, k1 = v ? kmask.w : kmask.y;
      g_mask[v * NROW + i] = (u01(xbits(k0, k1, i)) > 0.1f) ? 1.0f : 0.0f;
    } else if (i < 8320u) {
      // randint: k1,k2 = split(k_shift); higher from k1, lower from k2; 68 = 2^32 % 101
      unsigned b = i - 8192u;
      uint4 ks = v ? kshB : kshA;
      uint32_t hb = xbits(ks.x, ks.y, b);
      uint32_t lb = xbits(ks.z, ks.w, b);
      uint32_t off = ((hb % 101u) * 68u + (lb % 101u)) % 101u;
      g_shift[v * B_ + b] = -50 + (int)off;
    } else {
      unsigned j = i - 8320u;
      uint32_t k0 = v ? kscale.z : kscale.x, k1 = v ? kscale.w : kscale.y;
      float u = u01(xbits(k0, k1, j));
      const float span = 1.2f - 0.8f;
      g_scale[v * B_ + j] = fmaxf(0.8f, __fadd_rn(__fmul_rn(u, span), 0.8f));
    }
  }

  int row = blockIdx.x;
  const float4* xr = reinterpret_cast<const float4*>(x + ((size_t)row << 12));
  float s = 0.0f, q = 0.0f;
#pragma unroll
  for (int i = 0; i < 8; i++) {
    float4 v = xr[threadIdx.x + (i << 7)];
    s += (v.x + v.y) + (v.z + v.w);
    q += (v.x * v.x + v.y * v.y) + (v.z * v.z + v.w * v.w);
  }
#pragma unroll
  for (int o = 16; o; o >>= 1) {
    s += __shfl_down_sync(0xFFFFFFFFu, s, o);
    q += __shfl_down_sync(0xFFFFFFFFu, q, o);
  }
  __shared__ float ss[4], qq[4];
  int w = threadIdx.x >> 5;
  if ((threadIdx.x & 31) == 0) { ss[w] = s; qq[w] = q; }
  __syncthreads();
  if (threadIdx.x == 0) {
    s = ss[0] + ss[1] + ss[2] + ss[3];
    q = qq[0] + qq[1] + qq[2] + qq[3];
    float mean = s * (1.0f / 4096.0f);
    float var = (q - 4096.0f * mean * mean) * (1.0f / 4095.0f);
    // fold 0.1 (NOISE_STD) and sqrt(2) (from normal) into one factor
    g_sd[row] = 0.141421356237f * sqrtf(fmaxf(var, 0.0f));
  }
}

// ---------------- main: 4 consecutive elements per thread, both views ----------------
__global__ void __launch_bounds__(256) main_kernel(const float* __restrict__ x,
                                                   float* __restrict__ out,
                                                   uint4 knoise, uint32_t one) {
  unsigned t0 = (blockIdx.x * blockDim.x + threadIdx.x) * 4u;  // s%4==0
  int b = t0 >> 18;
  int s0 = t0 & 4095;
  int row = t0 >> 12;
  size_t base = (size_t)row << 12;
  float sd = g_sd[row];
  unsigned u0 = (unsigned)((s0 - g_shift[b]) & 4095);        // rolled start, view 0
  unsigned u1 = (unsigned)((s0 - g_shift[B_ + b]) & 4095);   // rolled start, view 1
  float ms0 = g_mask[row]        * g_scale[b];
  float ms1 = g_mask[NROW + row] * g_scale[B_ + b];
  const float* xb = x + base;

  // per-key derived constants (hoisted; warp-uniform)
  uint32_t ka0 = knoise.x, ka1 = knoise.y;
  uint32_t ka2 = ka0 ^ ka1 ^ 0x1BD11BDAu;
  uint32_t a_i1 = ka2 + 1u, a_i2 = ka0 + 2u, a_i3 = ka1 + 3u,
           a_i4 = ka2 + 4u, a_i5 = ka0 + 5u;
  uint32_t kb0 = knoise.z, kb1 = knoise.w;
  uint32_t kb2 = kb0 ^ kb1 ^ 0x1BD11BDAu;
  uint32_t b_i1 = kb2 + 1u, b_i2 = kb0 + 2u, b_i3 = kb1 + 3u,
           b_i4 = kb2 + 4u, b_i5 = kb0 + 5u;

  float4 o0, o1;
  float* p0 = &o0.x;
  float* p1 = &o1.x;
#pragma unroll
  for (int j = 0; j < 4; j++) {
    uint32_t wa = tf_xor(ka0, ka1, ka2, a_i1, a_i2, a_i3, a_i4, a_i5, t0 + j, one);
    uint32_t wb = tf_xor(kb0, kb1, kb2, b_i1, b_i2, b_i3, b_i4, b_i5, t0 + j, one);
    float z0 = erfinv_from_bits(wa);
    float z1 = erfinv_from_bits(wb);
    float xv0 = __ldg(xb + ((u0 + j) & 4095u));
    float xv1 = __ldg(xb + ((u1 + j) & 4095u));
    p0[j] = (xv0 + z0 * sd) * ms0;
    p1[j] = (xv1 + z1 * sd) * ms1;
  }

  *reinterpret_cast<float4*>(out + base + s0)        = o0;
  *reinterpret_cast<float4*>(out + NTOT + base + s0) = o1;
}

// ---------------- host-side Threefry for constant key derivation ----------------
static inline uint32_t h_rotl(uint32_t x, int r) { return (x << r) | (x >> (32 - r)); }
static void h_tf(uint32_t k0, uint32_t k1, uint32_t x0, uint32_t x1,
                 uint32_t* o0, uint32_t* o1) {
  uint32_t k2 = k0 ^ k1 ^ 0x1BD11BDAu;
  x0 += k0; x1 += k1;
#define HR(r) { x0 += x1; x1 = h_rotl(x1, r); x1 ^= x0; }
  HR(13) HR(15) HR(26) HR(6)  x0 += k1; x1 += k2 + 1u;
  HR(17) HR(29) HR(16) HR(24) x0 += k2; x1 += k0 + 2u;
  HR(13) HR(15) HR(26) HR(6)  x0 += k0; x1 += k1 + 3u;
  HR(17) HR(29) HR(16) HR(24) x0 += k1; x1 += k2 + 4u;
  HR(13) HR(15) HR(26) HR(6)  x0 += k2; x1 += k0 + 5u;
#undef HR
  *o0 = x0; *o1 = x1;
}

extern "C" void kernel_launch(void* const* d_in, const int* in_sizes, int n_in,
                              void* d_out, int out_size) {
  const float* x = (const float*)d_in[0];
  float* out = (float*)d_out;

  uint32_t vk[2][2];
  h_tf(0u, 42u, 0u, 1u, &vk[0][0], &vk[0][1]);
  h_tf(0u, 42u, 0u, 2u, &vk[1][0], &vk[1][1]);

  uint4 kshA, kshB, knoise, kmask, kscale;
  for (int v = 0; v < 2; v++) {
    uint32_t kj[4][2];
    for (uint32_t j = 0; j < 4; j++)
      h_tf(vk[v][0], vk[v][1], 0u, j, &kj[j][0], &kj[j][1]);
    uint32_t s1[2], s2[2];
    h_tf(kj[0][0], kj[0][1], 0u, 0u, &s1[0], &s1[1]);
    h_tf(kj[0][0], kj[0][1], 0u, 1u, &s2[0], &s2[1]);
    if (v == 0) {
      kshA.x = s1[0]; kshA.y = s1[1]; kshA.z = s2[0]; kshA.w = s2[1];
      knoise.x = kj[1][0]; knoise.y = kj[1][1];
      kmask.x  = kj[2][0]; kmask.y  = kj[2][1];
      kscale.x = kj[3][0]; kscale.y = kj[3][1];
    } else {
      kshB.x = s1[0]; kshB.y = s1[1]; kshB.z = s2[0]; kshB.w = s2[1];
      knoise.z = kj[1][0]; knoise.w = kj[1][1];
      kmask.z  = kj[2][0]; kmask.w  = kj[2][1];
      kscale.z = kj[3][0]; kscale.w = kj[3][1];
    }
  }

  prep_kernel<<<NROW, 128>>>(x, kshA, kshB, kmask, kscale);
  main_kernel<<<(unsigned)(NTOT / 4 / 256), 256>>>(x, out, knoise, 1u);
}

// round 11
// speedup vs baseline: 1.0861x; 1.0172x over previous
#include <cuda_runtime.h>
#include <cstdint>

// ---------------- constants ----------------
#define B_   128
#define C_   64
#define S_   4096
#define NROW (B_*C_)            // 8192
#define NTOT ((size_t)B_*C_*S_) // 33554432

// ---------------- scratch (no allocation allowed) ----------------
__device__ float g_sd[NROW];        // sqrt2 * 0.1 * per-row std (shared by views)
__device__ int   g_shift[2*B_];
__device__ float g_scale[2*B_];
__device__ float g_mask[2*NROW];

// ---------------- Threefry-2x32-20 (JAX-exact) ----------------
#define TF_R(x0,x1,r) { x0 += x1; x1 = __funnelshift_l(x1,x1,r); x1 ^= x0; }

// plain version (prep kernel, low volume, bit-exact)
__device__ __forceinline__ void tf_block0(uint32_t k0, uint32_t k1,
                                          uint32_t c1,
                                          uint32_t &o0, uint32_t &o1) {
  uint32_t k2 = k0 ^ k1 ^ 0x1BD11BDAu;
  uint32_t x0 = k0, x1 = c1 + k1;
  TF_R(x0,x1,13) TF_R(x0,x1,15) TF_R(x0,x1,26) TF_R(x0,x1,6)
  x0 += k1; x1 += k2 + 1u;
  TF_R(x0,x1,17) TF_R(x0,x1,29) TF_R(x0,x1,16) TF_R(x0,x1,24)
  x0 += k2; x1 += k0 + 2u;
  TF_R(x0,x1,13) TF_R(x0,x1,15) TF_R(x0,x1,26) TF_R(x0,x1,6)
  x0 += k0; x1 += k1 + 3u;
  TF_R(x0,x1,17) TF_R(x0,x1,29) TF_R(x0,x1,16) TF_R(x0,x1,24)
  x0 += k1; x1 += k2 + 4u;
  TF_R(x0,x1,13) TF_R(x0,x1,15) TF_R(x0,x1,26) TF_R(x0,x1,6)
  o0 = x0 + k2; o1 = x1 + k0 + 5u;
}

__device__ __forceinline__ uint32_t xbits(uint32_t k0, uint32_t k1, uint32_t i) {
  uint32_t o0, o1;
  tf_block0(k0, k1, i, o0, o1);
  return o0 ^ o1;
}

// ---- hot-path block: EVERY add as IMAD (fma pipe) via runtime `one`.
// alu pipe keeps only the unavoidable SHF + LOP3 per round.
// Output: (x0^x1)|0x200 — single 3-input LOP3. Forcing bit9 makes the
// downstream (bits>>9) mantissa odd, so x != -1 exactly and the clamp
// FMNMX is unnecessary. |Δx| <= 2.4e-7 vs reference (noise-only path).
#define MAD1(d,a) asm("mad.lo.u32 %0, %1, %2, %0;" : "+r"(d) : "r"(a), "r"(one))
#define TF_RM(r)  { MAD1(x0,x1); x1 = __funnelshift_l(x1,x1,r); x1 ^= x0; }

__device__ __forceinline__ uint32_t tf_xor(uint32_t k0, uint32_t k1,
                                           uint32_t k2,
                                           uint32_t i1, uint32_t i2,
                                           uint32_t i3, uint32_t i4,
                                           uint32_t i5,
                                           uint32_t c1, uint32_t one) {
  uint32_t x0 = k0, x1 = c1;
  MAD1(x1, k1);
  TF_RM(13) TF_RM(15) TF_RM(26) TF_RM(6)
  MAD1(x0, k1); MAD1(x1, i1);
  TF_RM(17) TF_RM(29) TF_RM(16) TF_RM(24)
  MAD1(x0, k2); MAD1(x1, i2);
  TF_RM(13) TF_RM(15) TF_RM(26) TF_RM(6)
  MAD1(x0, k0); MAD1(x1, i3);
  TF_RM(17) TF_RM(29) TF_RM(16) TF_RM(24)
  MAD1(x0, k1); MAD1(x1, i4);
  TF_RM(13) TF_RM(15) TF_RM(26) TF_RM(6)
  MAD1(x0, k2); MAD1(x1, i5);
  return (x0 ^ x1) | 0x200u;
}

// bits -> float in [0,1): JAX _uniform exact (prep path)
__device__ __forceinline__ float u01(uint32_t b) {
  return __uint_as_float((b >> 9) | 0x3F800000u) - 1.0f;
}

// erfinv(u_sym(bits)) WITHOUT sqrt(2) (folded into sd).
// bits->float-bits in ONE fma-pipe op: mad.hi(b, 2^23, 0x40000000)
//   = (b>>9) | 0x40000000 (disjoint bits -> add == or). bit0 set upstream.
// v = lg2(1-x^2) via MUFU. Central poly re-expanded in v (t = -ln2*v - 2.5
// folded into coefficients; algebraically exact). Tail (0.7% draws) as before.
__device__ __forceinline__ float erfinv_from_bits(uint32_t bts) {
  uint32_t xb;
  asm("mad.hi.u32 %0, %1, 0x800000U, 0x40000000U;" : "=r"(xb) : "r"(bts));
  float x = __uint_as_float(xb) - 3.0f;        // in (-1, 1), never +-1
  float v = __log2f(fmaf(-x, x, 1.0f));        // lg2(1 - x^2) in [-21.4, 0)
  float p;
  if (v > -7.2134752f) {                       // w < 5
    p = 5.0456135e-5f;
    p = fmaf(p, v, 1.1454495e-3f);
    p = fmaf(p, v, 6.4486591e-3f);
    p = fmaf(p, v, -0.15967367f);
    p = fmaf(p, v, 0.88682485f);
  } else {
    float w = -0.69314718f * v;
    float t = sqrtf(w) - 3.0f;
    p = 0.00573950773f;
    p = fmaf(p, t, -0.0076224613f);
    p = fmaf(p, t, 0.00943887047f);
    p = fmaf(p, t, 1.00167406f);
    p = fmaf(p, t, 2.83297682f);
  }
  return p * x;
}

// ---------------- fused prep: per-row std + shifts/masks/scales ----------------
__global__ void prep_kernel(const float* __restrict__ x,
                            uint4 kshA, uint4 kshB, uint4 kmask, uint4 kscale) {
  unsigned gt = blockIdx.x * blockDim.x + threadIdx.x;
  if (gt < 2u * 8448u) {
    int v = (gt >= 8448u);
    unsigned i = gt - (unsigned)v * 8448u;
    if (i < 8192u) {
      uint32_t k0 = v ? kmask.z : kmask.x, k1 = v ? kmask.w : kmask.y;
      g_mask[v * NROW + i] = (u01(xbits(k0, k1, i)) > 0.1f) ? 1.0f : 0.0f;
    } else if (i < 8320u) {
      // randint: k1,k2 = split(k_shift); higher from k1, lower from k2; 68 = 2^32 % 101
      unsigned b = i - 8192u;
      uint4 ks = v ? kshB : kshA;
      uint32_t hb = xbits(ks.x, ks.y, b);
      uint32_t lb = xbits(ks.z, ks.w, b);
      uint32_t off = ((hb % 101u) * 68u + (lb % 101u)) % 101u;
      g_shift[v * B_ + b] = -50 + (int)off;
    } else {
      unsigned j = i - 8320u;
      uint32_t k0 = v ? kscale.z : kscale.x, k1 = v ? kscale.w : kscale.y;
      float u = u01(xbits(k0, k1, j));
      const float span = 1.2f - 0.8f;
      g_scale[v * B_ + j] = fmaxf(0.8f, __fadd_rn(__fmul_rn(u, span), 0.8f));
    }
  }

  int row = blockIdx.x;
  const float4* xr = reinterpret_cast<const float4*>(x + ((size_t)row << 12));
  float s = 0.0f, q = 0.0f;
#pragma unroll
  for (int i = 0; i < 8; i++) {
    float4 v = xr[threadIdx.x + (i << 7)];
    s += (v.x + v.y) + (v.z + v.w);
    q += (v.x * v.x + v.y * v.y) + (v.z * v.z + v.w * v.w);
  }
#pragma unroll
  for (int o = 16; o; o >>= 1) {
    s += __shfl_down_sync(0xFFFFFFFFu, s, o);
    q += __shfl_down_sync(0xFFFFFFFFu, q, o);
  }
  __shared__ float ss[4], qq[4];
  int w = threadIdx.x >> 5;
  if ((threadIdx.x & 31) == 0) { ss[w] = s; qq[w] = q; }
  __syncthreads();
  if (threadIdx.x == 0) {
    s = ss[0] + ss[1] + ss[2] + ss[3];
    q = qq[0] + qq[1] + qq[2] + qq[3];
    float mean = s * (1.0f / 4096.0f);
    float var = (q - 4096.0f * mean * mean) * (1.0f / 4095.0f);
    // fold 0.1 (NOISE_STD) and sqrt(2) (from normal) into one factor
    g_sd[row] = 0.141421356237f * sqrtf(fmaxf(var, 0.0f));
  }
}

// ---------------- main: 4 consecutive elements per thread, both views ----------------
__global__ void __launch_bounds__(256) main_kernel(const float* __restrict__ x,
                                                   float* __restrict__ out,
                                                   uint4 knoise, uint32_t one) {
  unsigned t0 = (blockIdx.x * blockDim.x + threadIdx.x) * 4u;  // s%4==0
  int b = t0 >> 18;
  int s0 = t0 & 4095;
  int row = t0 >> 12;
  size_t base = (size_t)row << 12;
  float sd = g_sd[row];
  unsigned u0 = (unsigned)((s0 - g_shift[b]) & 4095);        // rolled start, view 0
  unsigned u1 = (unsigned)((s0 - g_shift[B_ + b]) & 4095);   // rolled start, view 1
  float ms0 = g_mask[row]        * g_scale[b];
  float ms1 = g_mask[NROW + row] * g_scale[B_ + b];
  const float* xb = x + base;

  // per-key derived constants (hoisted; warp-uniform)
  uint32_t ka0 = knoise.x, ka1 = knoise.y;
  uint32_t ka2 = ka0 ^ ka1 ^ 0x1BD11BDAu;
  uint32_t a_i1 = ka2 + 1u, a_i2 = ka0 + 2u, a_i3 = ka1 + 3u,
           a_i4 = ka2 + 4u, a_i5 = ka0 + 5u;
  uint32_t kb0 = knoise.z, kb1 = knoise.w;
  uint32_t kb2 = kb0 ^ kb1 ^ 0x1BD11BDAu;
  uint32_t b_i1 = kb2 + 1u, b_i2 = kb0 + 2u, b_i3 = kb1 + 3u,
           b_i4 = kb2 + 4u, b_i5 = kb0 + 5u;

  float4 o0, o1;
  float* p0 = &o0.x;
  float* p1 = &o1.x;
#pragma unroll
  for (int j = 0; j < 4; j++) {
    uint32_t wa = tf_xor(ka0, ka1, ka2, a_i1, a_i2, a_i3, a_i4, a_i5, t0 + j, one);
    uint32_t wb = tf_xor(kb0, kb1, kb2, b_i1, b_i2, b_i3, b_i4, b_i5, t0 + j, one);
    float z0 = erfinv_from_bits(wa);
    float z1 = erfinv_from_bits(wb);
    float xv0 = __ldg(xb + ((u0 + j) & 4095u));
    float xv1 = __ldg(xb + ((u1 + j) & 4095u));
    p0[j] = (xv0 + z0 * sd) * ms0;
    p1[j] = (xv1 + z1 * sd) * ms1;
  }

  *reinterpret_cast<float4*>(out + base + s0)        = o0;
  *reinterpret_cast<float4*>(out + NTOT + base + s0) = o1;
}

// ---------------- host-side Threefry for constant key derivation ----------------
static inline uint32_t h_rotl(uint32_t x, int r) { return (x << r) | (x >> (32 - r)); }
static void h_tf(uint32_t k0, uint32_t k1, uint32_t x0, uint32_t x1,
                 uint32_t* o0, uint32_t* o1) {
  uint32_t k2 = k0 ^ k1 ^ 0x1BD11BDAu;
  x0 += k0; x1 += k1;
#define HR(r) { x0 += x1; x1 = h_rotl(x1, r); x1 ^= x0; }
  HR(13) HR(15) HR(26) HR(6)  x0 += k1; x1 += k2 + 1u;
  HR(17) HR(29) HR(16) HR(24) x0 += k2; x1 += k0 + 2u;
  HR(13) HR(15) HR(26) HR(6)  x0 += k0; x1 += k1 + 3u;
  HR(17) HR(29) HR(16) HR(24) x0 += k1; x1 += k2 + 4u;
  HR(13) HR(15) HR(26) HR(6)  x0 += k2; x1 += k0 + 5u;
#undef HR
  *o0 = x0; *o1 = x1;
}

extern "C" void kernel_launch(void* const* d_in, const int* in_sizes, int n_in,
                              void* d_out, int out_size) {
  const float* x = (const float*)d_in[0];
  float* out = (float*)d_out;

  uint32_t vk[2][2];
  h_tf(0u, 42u, 0u, 1u, &vk[0][0], &vk[0][1]);
  h_tf(0u, 42u, 0u, 2u, &vk[1][0], &vk[1][1]);

  uint4 kshA, kshB, knoise, kmask, kscale;
  for (int v = 0; v < 2; v++) {
    uint32_t kj[4][2];
    for (uint32_t j = 0; j < 4; j++)
      h_tf(vk[v][0], vk[v][1], 0u, j, &kj[j][0], &kj[j][1]);
    uint32_t s1[2], s2[2];
    h_tf(kj[0][0], kj[0][1], 0u, 0u, &s1[0], &s1[1]);
    h_tf(kj[0][0], kj[0][1], 0u, 1u, &s2[0], &s2[1]);
    if (v == 0) {
      kshA.x = s1[0]; kshA.y = s1[1]; kshA.z = s2[0]; kshA.w = s2[1];
      knoise.x = kj[1][0]; knoise.y = kj[1][1];
      kmask.x  = kj[2][0]; kmask.y  = kj[2][1];
      kscale.x = kj[3][0]; kscale.y = kj[3][1];
    } else {
      kshB.x = s1[0]; kshB.y = s1[1]; kshB.z = s2[0]; kshB.w = s2[1];
      knoise.z = kj[1][0]; knoise.w = kj[1][1];
      kmask.z  = kj[2][0]; kmask.w  = kj[2][1];
      kscale.z = kj[3][0]; kscale.w = kj[3][1];
    }
  }

  prep_kernel<<<NROW, 128>>>(x, kshA, kshB, kmask, kscale);
  main_kernel<<<(unsigned)(NTOT / 4 / 256), 256>>>(x, out, knoise, 1u);
}

// round 12
// speedup vs baseline: 1.1182x; 1.0296x over previous
#include <cuda_runtime.h>
#include <cstdint>

// ---------------- constants ----------------
#define B_   128
#define C_   64
#define S_   4096
#define NROW (B_*C_)            // 8192
#define NTOT ((size_t)B_*C_*S_) // 33554432

// ---------------- scratch (no allocation allowed) ----------------
__device__ float g_sd[NROW];        // sqrt2 * 0.1 * per-row std (shared by views)
__device__ int   g_shift[2*B_];
__device__ float g_scale[2*B_];
__device__ float g_mask[2*NROW];

// ---------------- Threefry-2x32-20 (JAX-exact) ----------------
#define TF_R(x0,x1,r) { x0 += x1; x1 = __funnelshift_l(x1,x1,r); x1 ^= x0; }

// plain version (prep kernel, low volume, bit-exact)
__device__ __forceinline__ void tf_block0(uint32_t k0, uint32_t k1,
                                          uint32_t c1,
                                          uint32_t &o0, uint32_t &o1) {
  uint32_t k2 = k0 ^ k1 ^ 0x1BD11BDAu;
  uint32_t x0 = k0, x1 = c1 + k1;
  TF_R(x0,x1,13) TF_R(x0,x1,15) TF_R(x0,x1,26) TF_R(x0,x1,6)
  x0 += k1; x1 += k2 + 1u;
  TF_R(x0,x1,17) TF_R(x0,x1,29) TF_R(x0,x1,16) TF_R(x0,x1,24)
  x0 += k2; x1 += k0 + 2u;
  TF_R(x0,x1,13) TF_R(x0,x1,15) TF_R(x0,x1,26) TF_R(x0,x1,6)
  x0 += k0; x1 += k1 + 3u;
  TF_R(x0,x1,17) TF_R(x0,x1,29) TF_R(x0,x1,16) TF_R(x0,x1,24)
  x0 += k1; x1 += k2 + 4u;
  TF_R(x0,x1,13) TF_R(x0,x1,15) TF_R(x0,x1,26) TF_R(x0,x1,6)
  o0 = x0 + k2; o1 = x1 + k0 + 5u;
}

__device__ __forceinline__ uint32_t xbits(uint32_t k0, uint32_t k1, uint32_t i) {
  uint32_t o0, o1;
  tf_block0(k0, k1, i, o0, o1);
  return o0 ^ o1;
}

// ---- hot-path block: EVERY add as IMAD (fma pipe) via runtime `one`.
// alu pipe keeps only the unavoidable SHF + LOP3 per round (structural floor).
// Output: (x0^x1)|0x200 — single 3-input LOP3; forces the uniform's low
// mantissa bit so x != -1 exactly (no clamp needed). |Δx| <= 2.4e-7.
#define MAD1(d,a) asm("mad.lo.u32 %0, %1, %2, %0;" : "+r"(d) : "r"(a), "r"(one))
#define TF_RM(r)  { MAD1(x0,x1); x1 = __funnelshift_l(x1,x1,r); x1 ^= x0; }

__device__ __forceinline__ uint32_t tf_xor(uint32_t k0, uint32_t k1,
                                           uint32_t k2,
                                           uint32_t i1, uint32_t i2,
                                           uint32_t i3, uint32_t i4,
                                           uint32_t i5,
                                           uint32_t c1, uint32_t one) {
  uint32_t x0 = k0, x1 = c1;
  MAD1(x1, k1);
  TF_RM(13) TF_RM(15) TF_RM(26) TF_RM(6)
  MAD1(x0, k1); MAD1(x1, i1);
  TF_RM(17) TF_RM(29) TF_RM(16) TF_RM(24)
  MAD1(x0, k2); MAD1(x1, i2);
  TF_RM(13) TF_RM(15) TF_RM(26) TF_RM(6)
  MAD1(x0, k0); MAD1(x1, i3);
  TF_RM(17) TF_RM(29) TF_RM(16) TF_RM(24)
  MAD1(x0, k1); MAD1(x1, i4);
  TF_RM(13) TF_RM(15) TF_RM(26) TF_RM(6)
  MAD1(x0, k2); MAD1(x1, i5);
  return (x0 ^ x1) | 0x200u;
}

// bits -> float in [0,1): JAX _uniform exact (prep path)
__device__ __forceinline__ float u01(uint32_t b) {
  return __uint_as_float((b >> 9) | 0x3F800000u) - 1.0f;
}

// erfinv(u_sym(bits)) WITHOUT sqrt(2) (folded into sd).
// bits->float-bits in ONE fma-pipe op: mad.hi(b, 2^23, 0x40000000).
// v = lg2(1-x^2) via MUFU; central poly re-expanded in v (exact refactor);
// tail (0.34% of draws) unchanged.
__device__ __forceinline__ float erfinv_from_bits(uint32_t bts) {
  uint32_t xb;
  asm("mad.hi.u32 %0, %1, 0x800000U, 0x40000000U;" : "=r"(xb) : "r"(bts));
  float x = __uint_as_float(xb) - 3.0f;        // in (-1, 1), never +-1
  float v = __log2f(fmaf(-x, x, 1.0f));        // lg2(1 - x^2) in [-21.4, 0)
  float p;
  if (v > -7.2134752f) {                       // w < 5
    p = 5.0456135e-5f;
    p = fmaf(p, v, 1.1454495e-3f);
    p = fmaf(p, v, 6.4486591e-3f);
    p = fmaf(p, v, -0.15967367f);
    p = fmaf(p, v, 0.88682485f);
  } else {
    float w = -0.69314718f * v;
    float t = sqrtf(w) - 3.0f;
    p = 0.00573950773f;
    p = fmaf(p, t, -0.0076224613f);
    p = fmaf(p, t, 0.00943887047f);
    p = fmaf(p, t, 1.00167406f);
    p = fmaf(p, t, 2.83297682f);
  }
  return p * x;
}

// ---------------- fused prep: per-row std + shifts/masks/scales ----------------
__global__ void prep_kernel(const float* __restrict__ x,
                            uint4 kshA, uint4 kshB, uint4 kmask, uint4 kscale) {
  unsigned gt = blockIdx.x * blockDim.x + threadIdx.x;
  if (gt < 2u * 8448u) {
    int v = (gt >= 8448u);
    unsigned i = gt - (unsigned)v * 8448u;
    if (i < 8192u) {
      uint32_t k0 = v ? kmask.z : kmask.x, k1 = v ? kmask.w : kmask.y;
      g_mask[v * NROW + i] = (u01(xbits(k0, k1, i)) > 0.1f) ? 1.0f : 0.0f;
    } else if (i < 8320u) {
      // randint: k1,k2 = split(k_shift); higher from k1, lower from k2; 68 = 2^32 % 101
      unsigned b = i - 8192u;
      uint4 ks = v ? kshB : kshA;
      uint32_t hb = xbits(ks.x, ks.y, b);
      uint32_t lb = xbits(ks.z, ks.w, b);
      uint32_t off = ((hb % 101u) * 68u + (lb % 101u)) % 101u;
      g_shift[v * B_ + b] = -50 + (int)off;
    } else {
      unsigned j = i - 8320u;
      uint32_t k0 = v ? kscale.z : kscale.x, k1 = v ? kscale.w : kscale.y;
      float u = u01(xbits(k0, k1, j));
      const float span = 1.2f - 0.8f;
      g_scale[v * B_ + j] = fmaxf(0.8f, __fadd_rn(__fmul_rn(u, span), 0.8f));
    }
  }

  int row = blockIdx.x;
  const float4* xr = reinterpret_cast<const float4*>(x + ((size_t)row << 12));
  float s = 0.0f, q = 0.0f;
#pragma unroll
  for (int i = 0; i < 8; i++) {
    float4 v = xr[threadIdx.x + (i << 7)];
    s += (v.x + v.y) + (v.z + v.w);
    q += (v.x * v.x + v.y * v.y) + (v.z * v.z + v.w * v.w);
  }
#pragma unroll
  for (int o = 16; o; o >>= 1) {
    s += __shfl_down_sync(0xFFFFFFFFu, s, o);
    q += __shfl_down_sync(0xFFFFFFFFu, q, o);
  }
  __shared__ float ss[4], qq[4];
  int w = threadIdx.x >> 5;
  if ((threadIdx.x & 31) == 0) { ss[w] = s; qq[w] = q; }
  __syncthreads();
  if (threadIdx.x == 0) {
    s = ss[0] + ss[1] + ss[2] + ss[3];
    q = qq[0] + qq[1] + qq[2] + qq[3];
    float mean = s * (1.0f / 4096.0f);
    float var = (q - 4096.0f * mean * mean) * (1.0f / 4095.0f);
    // fold 0.1 (NOISE_STD) and sqrt(2) (from normal) into one factor
    g_sd[row] = 0.141421356237f * sqrtf(fmaxf(var, 0.0f));
  }
}

// ---------------- main: 8 consecutive elements per thread, both views ----------------
__global__ void __launch_bounds__(256) main_kernel(const float* __restrict__ x,
                                                   float* __restrict__ out,
                                                   uint4 knoise, uint32_t one) {
  unsigned t0 = (blockIdx.x * blockDim.x + threadIdx.x) * 8u;  // s%8==0
  int b = t0 >> 18;
  int s0 = t0 & 4095;
  int row = t0 >> 12;
  size_t base = (size_t)row << 12;
  float sd = g_sd[row];
  unsigned u0 = (unsigned)((s0 - g_shift[b]) & 4095);        // rolled start, view 0
  unsigned u1 = (unsigned)((s0 - g_shift[B_ + b]) & 4095);   // rolled start, view 1
  float ms0 = g_mask[row]        * g_scale[b];
  float ms1 = g_mask[NROW + row] * g_scale[B_ + b];
  const float* xb = x + base;

  // per-key derived constants (hoisted; warp-uniform)
  uint32_t ka0 = knoise.x, ka1 = knoise.y;
  uint32_t ka2 = ka0 ^ ka1 ^ 0x1BD11BDAu;
  uint32_t a_i1 = ka2 + 1u, a_i2 = ka0 + 2u, a_i3 = ka1 + 3u,
           a_i4 = ka2 + 4u, a_i5 = ka0 + 5u;
  uint32_t kb0 = knoise.z, kb1 = knoise.w;
  uint32_t kb2 = kb0 ^ kb1 ^ 0x1BD11BDAu;
  uint32_t b_i1 = kb2 + 1u, b_i2 = kb0 + 2u, b_i3 = kb1 + 3u,
           b_i4 = kb2 + 4u, b_i5 = kb0 + 5u;

#pragma unroll
  for (int g = 0; g < 2; g++) {                 // two float4 groups
    unsigned tg = t0 + 4u * g;
    float4 o0, o1;
    float* p0 = &o0.x;
    float* p1 = &o1.x;
#pragma unroll
    for (int j = 0; j < 4; j++) {
      unsigned e = 4u * g + j;
      uint32_t wa = tf_xor(ka0, ka1, ka2, a_i1, a_i2, a_i3, a_i4, a_i5, tg + j, one);
      uint32_t wb = tf_xor(kb0, kb1, kb2, b_i1, b_i2, b_i3, b_i4, b_i5, tg + j, one);
      float z0 = erfinv_from_bits(wa);
      float z1 = erfinv_from_bits(wb);
      float xv0 = __ldg(xb + ((u0 + e) & 4095u));
      float xv1 = __ldg(xb + ((u1 + e) & 4095u));
      p0[j] = (xv0 + z0 * sd) * ms0;
      p1[j] = (xv1 + z1 * sd) * ms1;
    }
    *reinterpret_cast<float4*>(out + base + s0 + 4u * g)        = o0;
    *reinterpret_cast<float4*>(out + NTOT + base + s0 + 4u * g) = o1;
  }
}

// ---------------- host-side Threefry for constant key derivation ----------------
static inline uint32_t h_rotl(uint32_t x, int r) { return (x << r) | (x >> (32 - r)); }
static void h_tf(uint32_t k0, uint32_t k1, uint32_t x0, uint32_t x1,
                 uint32_t* o0, uint32_t* o1) {
  uint32_t k2 = k0 ^ k1 ^ 0x1BD11BDAu;
  x0 += k0; x1 += k1;
#define HR(r) { x0 += x1; x1 = h_rotl(x1, r); x1 ^= x0; }
  HR(13) HR(15) HR(26) HR(6)  x0 += k1; x1 += k2 + 1u;
  HR(17) HR(29) HR(16) HR(24) x0 += k2; x1 += k0 + 2u;
  HR(13) HR(15) HR(26) HR(6)  x0 += k0; x1 += k1 + 3u;
  HR(17) HR(29) HR(16) HR(24) x0 += k1; x1 += k2 + 4u;
  HR(13) HR(15) HR(26) HR(6)  x0 += k2; x1 += k0 + 5u;
#undef HR
  *o0 = x0; *o1 = x1;
}

extern "C" void kernel_launch(void* const* d_in, const int* in_sizes, int n_in,
                              void* d_out, int out_size) {
  const float* x = (const float*)d_in[0];
  float* out = (float*)d_out;

  uint32_t vk[2][2];
  h_tf(0u, 42u, 0u, 1u, &vk[0][0], &vk[0][1]);
  h_tf(0u, 42u, 0u, 2u, &vk[1][0], &vk[1][1]);

  uint4 kshA, kshB, knoise, kmask, kscale;
  for (int v = 0; v < 2; v++) {
    uint32_t kj[4][2];
    for (uint32_t j = 0; j < 4; j++)
      h_tf(vk[v][0], vk[v][1], 0u, j, &kj[j][0], &kj[j][1]);
    uint32_t s1[2], s2[2];
    h_tf(kj[0][0], kj[0][1], 0u, 0u, &s1[0], &s1[1]);
    h_tf(kj[0][0], kj[0][1], 0u, 1u, &s2[0], &s2[1]);
    if (v == 0) {
      kshA.x = s1[0]; kshA.y = s1[1]; kshA.z = s2[0]; kshA.w = s2[1];
      knoise.x = kj[1][0]; knoise.y = kj[1][1];
      kmask.x  = kj[2][0]; kmask.y  = kj[2][1];
      kscale.x = kj[3][0]; kscale.y = kj[3][1];
    } else {
      kshB.x = s1[0]; kshB.y = s1[1]; kshB.z = s2[0]; kshB.w = s2[1];
      knoise.z = kj[1][0]; knoise.w = kj[1][1];
      kmask.z  = kj[2][0]; kmask.w  = kj[2][1];
      kscale.z = kj[3][0]; kscale.w = kj[3][1];
    }
  }

  prep_kernel<<<NROW, 128>>>(x, kshA, kshB, kmask, kscale);
  main_kernel<<<(unsigned)(NTOT / 8 / 256), 256>>>(x, out, knoise, 1u);
}

// round 13
// speedup vs baseline: 1.1344x; 1.0145x over previous
#include <cuda_runtime.h>
#include <cstdint>

// ---------------- constants ----------------
#define B_   128
#define C_   64
#define S_   4096
#define NROW (B_*C_)            // 8192
#define NTOT ((size_t)B_*C_*S_) // 33554432

// ---------------- scratch (no allocation allowed) ----------------
__device__ float g_sd[NROW];        // sqrt2 * 0.1 * per-row std (shared by views)
__device__ int   g_shift[2*B_];
__device__ float g_scale[2*B_];
__device__ float g_mask[2*NROW];

// ---------------- Threefry-2x32-20 (JAX-exact) ----------------
#define TF_R(x0,x1,r) { x0 += x1; x1 = __funnelshift_l(x1,x1,r); x1 ^= x0; }

// plain version (prep kernel, low volume, bit-exact)
__device__ __forceinline__ void tf_block0(uint32_t k0, uint32_t k1,
                                          uint32_t c1,
                                          uint32_t &o0, uint32_t &o1) {
  uint32_t k2 = k0 ^ k1 ^ 0x1BD11BDAu;
  uint32_t x0 = k0, x1 = c1 + k1;
  TF_R(x0,x1,13) TF_R(x0,x1,15) TF_R(x0,x1,26) TF_R(x0,x1,6)
  x0 += k1; x1 += k2 + 1u;
  TF_R(x0,x1,17) TF_R(x0,x1,29) TF_R(x0,x1,16) TF_R(x0,x1,24)
  x0 += k2; x1 += k0 + 2u;
  TF_R(x0,x1,13) TF_R(x0,x1,15) TF_R(x0,x1,26) TF_R(x0,x1,6)
  x0 += k0; x1 += k1 + 3u;
  TF_R(x0,x1,17) TF_R(x0,x1,29) TF_R(x0,x1,16) TF_R(x0,x1,24)
  x0 += k1; x1 += k2 + 4u;
  TF_R(x0,x1,13) TF_R(x0,x1,15) TF_R(x0,x1,26) TF_R(x0,x1,6)
  o0 = x0 + k2; o1 = x1 + k0 + 5u;
}

__device__ __forceinline__ uint32_t xbits(uint32_t k0, uint32_t k1, uint32_t i) {
  uint32_t o0, o1;
  tf_block0(k0, k1, i, o0, o1);
  return o0 ^ o1;
}

// ---- hot-path block: EVERY add as IMAD (fma pipe) via runtime `one`.
// alu pipe keeps only the unavoidable SHF + LOP3 per round (structural floor).
// x1 arrives pre-initialized (counter + k1 hoisted by caller).
// Output: (x0^x1)|0x200 — single 3-input LOP3; forces the uniform's low
// mantissa bit so x != -1 exactly (no clamp needed). |Δx| <= 2.4e-7.
#define MAD1(d,a) asm("mad.lo.u32 %0, %1, %2, %0;" : "+r"(d) : "r"(a), "r"(one))
#define TF_RM(r)  { MAD1(x0,x1); x1 = __funnelshift_l(x1,x1,r); x1 ^= x0; }

__device__ __forceinline__ uint32_t tf_xor(uint32_t k0, uint32_t k1,
                                           uint32_t k2,
                                           uint32_t i1, uint32_t i2,
                                           uint32_t i3, uint32_t i4,
                                           uint32_t i5,
                                           uint32_t x1init, uint32_t one) {
  uint32_t x0 = k0, x1 = x1init;
  TF_RM(13) TF_RM(15) TF_RM(26) TF_RM(6)
  MAD1(x0, k1); MAD1(x1, i1);
  TF_RM(17) TF_RM(29) TF_RM(16) TF_RM(24)
  MAD1(x0, k2); MAD1(x1, i2);
  TF_RM(13) TF_RM(15) TF_RM(26) TF_RM(6)
  MAD1(x0, k0); MAD1(x1, i3);
  TF_RM(17) TF_RM(29) TF_RM(16) TF_RM(24)
  MAD1(x0, k1); MAD1(x1, i4);
  TF_RM(13) TF_RM(15) TF_RM(26) TF_RM(6)
  MAD1(x0, k2); MAD1(x1, i5);
  return (x0 ^ x1) | 0x200u;
}

// bits -> float in [0,1): JAX _uniform exact (prep path)
__device__ __forceinline__ float u01(uint32_t b) {
  return __uint_as_float((b >> 9) | 0x3F800000u) - 1.0f;
}

// ---------------- packed f32x2 helpers ----------------
__device__ __forceinline__ uint64_t pk2(float lo, float hi) {
  uint64_t r; asm("mov.b64 %0, {%1, %2};" : "=l"(r) : "f"(lo), "f"(hi)); return r;
}
#define FMA2(d,a,b,c) asm("fma.rn.f32x2 %0, %1, %2, %3;" : "=l"(d) : "l"(a), "l"(b), "l"(c))
#define MUL2(d,a,b)   asm("mul.rn.f32x2 %0, %1, %2;"     : "=l"(d) : "l"(a), "l"(b))

// rare tail branch (w >= 5; ~0.34% of draws)
__device__ __forceinline__ float erfinv_tail(float v) {
  float w = -0.69314718f * v;
  float t = sqrtf(w) - 3.0f;
  float p = 0.00573950773f;
  p = fmaf(p, t, -0.0076224613f);
  p = fmaf(p, t, 0.00943887047f);
  p = fmaf(p, t, 1.00167406f);
  p = fmaf(p, t, 2.83297682f);
  return p;
}

// erfinv for the two views of one element, central poly packed f32x2.
// Lane-wise IEEE-identical to the R12 scalar version.
__device__ __forceinline__ void erfinv_pair(uint32_t ba, uint32_t bb,
                                            float &za, float &zb) {
  uint32_t ia, ib;
  asm("mad.hi.u32 %0, %1, 0x800000U, 0x40000000U;" : "=r"(ia) : "r"(ba));
  asm("mad.hi.u32 %0, %1, 0x800000U, 0x40000000U;" : "=r"(ib) : "r"(bb));
  float xa = __uint_as_float(ia) - 3.0f;        // in (-1,1), never +-1
  float xb = __uint_as_float(ib) - 3.0f;
  float va = __log2f(fmaf(-xa, xa, 1.0f));      // lg2(1 - x^2) < 0
  float vb = __log2f(fmaf(-xb, xb, 1.0f));
  uint64_t vv = pk2(va, vb);
  uint64_t xx = pk2(xa, xb);
  uint64_t pp = pk2(5.0456135e-5f, 5.0456135e-5f);
  const uint64_t c1 = pk2(1.1454495e-3f, 1.1454495e-3f);
  const uint64_t c2 = pk2(6.4486591e-3f, 6.4486591e-3f);
  const uint64_t c3 = pk2(-0.15967367f, -0.15967367f);
  const uint64_t c4 = pk2(0.88682485f, 0.88682485f);
  FMA2(pp, pp, vv, c1);
  FMA2(pp, pp, vv, c2);
  FMA2(pp, pp, vv, c3);
  FMA2(pp, pp, vv, c4);
  uint64_t zz;
  MUL2(zz, pp, xx);
  asm("mov.b64 {%0, %1}, %2;" : "=f"(za), "=f"(zb) : "l"(zz));
  if (va <= -7.2134752f) za = erfinv_tail(va) * xa;   // w >= 5 tail fixup
  if (vb <= -7.2134752f) zb = erfinv_tail(vb) * xb;
}

// ---------------- fused prep: per-row std + shifts/masks/scales ----------------
__global__ void prep_kernel(const float* __restrict__ x,
                            uint4 kshA, uint4 kshB, uint4 kmask, uint4 kscale) {
  unsigned gt = blockIdx.x * blockDim.x + threadIdx.x;
  if (gt < 2u * 8448u) {
    int v = (gt >= 8448u);
    unsigned i = gt - (unsigned)v * 8448u;
    if (i < 8192u) {
      uint32_t k0 = v ? kmask.z : kmask.x, k1 = v ? kmask.w : kmask.y;
      g_mask[v * NROW + i] = (u01(xbits(k0, k1, i)) > 0.1f) ? 1.0f : 0.0f;
    } else if (i < 8320u) {
      // randint: k1,k2 = split(k_shift); higher from k1, lower from k2; 68 = 2^32 % 101
      unsigned b = i - 8192u;
      uint4 ks = v ? kshB : kshA;
      uint32_t hb = xbits(ks.x, ks.y, b);
      uint32_t lb = xbits(ks.z, ks.w, b);
      uint32_t off = ((hb % 101u) * 68u + (lb % 101u)) % 101u;
      g_shift[v * B_ + b] = -50 + (int)off;
    } else {
      unsigned j = i - 8320u;
      uint32_t k0 = v ? kscale.z : kscale.x, k1 = v ? kscale.w : kscale.y;
      float u = u01(xbits(k0, k1, j));
      const float span = 1.2f - 0.8f;
      g_scale[v * B_ + j] = fmaxf(0.8f, __fadd_rn(__fmul_rn(u, span), 0.8f));
    }
  }

  int row = blockIdx.x;
  const float4* xr = reinterpret_cast<const float4*>(x + ((size_t)row << 12));
  float s = 0.0f, q = 0.0f;
#pragma unroll
  for (int i = 0; i < 8; i++) {
    float4 v = xr[threadIdx.x + (i << 7)];
    s += (v.x + v.y) + (v.z + v.w);
    q += (v.x * v.x + v.y * v.y) + (v.z * v.z + v.w * v.w);
  }
#pragma unroll
  for (int o = 16; o; o >>= 1) {
    s += __shfl_down_sync(0xFFFFFFFFu, s, o);
    q += __shfl_down_sync(0xFFFFFFFFu, q, o);
  }
  __shared__ float ss[4], qq[4];
  int w = threadIdx.x >> 5;
  if ((threadIdx.x & 31) == 0) { ss[w] = s; qq[w] = q; }
  __syncthreads();
  if (threadIdx.x == 0) {
    s = ss[0] + ss[1] + ss[2] + ss[3];
    q = qq[0] + qq[1] + qq[2] + qq[3];
    float mean = s * (1.0f / 4096.0f);
    float var = (q - 4096.0f * mean * mean) * (1.0f / 4095.0f);
    // fold 0.1 (NOISE_STD) and sqrt(2) (from normal) into one factor
    g_sd[row] = 0.141421356237f * sqrtf(fmaxf(var, 0.0f));
  }
}

// ---------------- main: 8 consecutive elements per thread, both views ----------------
__global__ void __launch_bounds__(256) main_kernel(const float* __restrict__ x,
                                                   float* __restrict__ out,
                                                   uint4 knoise, uint32_t one) {
  unsigned t0 = (blockIdx.x * blockDim.x + threadIdx.x) * 8u;  // s%8==0
  int b = t0 >> 18;
  int s0 = t0 & 4095;
  int row = t0 >> 12;
  size_t base = (size_t)row << 12;
  float sd = g_sd[row];
  unsigned u0 = (unsigned)((s0 - g_shift[b]) & 4095);        // rolled start, view 0
  unsigned u1 = (unsigned)((s0 - g_shift[B_ + b]) & 4095);   // rolled start, view 1
  float ms0 = g_mask[row]        * g_scale[b];
  float ms1 = g_mask[NROW + row] * g_scale[B_ + b];
  const float* xb = x + base;

  // per-key derived constants (hoisted; warp-uniform)
  uint32_t ka0 = knoise.x, ka1 = knoise.y;
  uint32_t ka2 = ka0 ^ ka1 ^ 0x1BD11BDAu;
  uint32_t a_i1 = ka2 + 1u, a_i2 = ka0 + 2u, a_i3 = ka1 + 3u,
           a_i4 = ka2 + 4u, a_i5 = ka0 + 5u;
  uint32_t kb0 = knoise.z, kb1 = knoise.w;
  uint32_t kb2 = kb0 ^ kb1 ^ 0x1BD11BDAu;
  uint32_t b_i1 = kb2 + 1u, b_i2 = kb0 + 2u, b_i3 = kb1 + 3u,
           b_i4 = kb2 + 4u, b_i5 = kb0 + 5u;
  uint32_t tka = t0 + ka1;   // hoisted counter+key for view 0
  uint32_t tkb = t0 + kb1;   // hoisted counter+key for view 1

#pragma unroll
  for (int g = 0; g < 2; g++) {                 // two float4 groups
    float4 o0, o1;
    float* p0 = &o0.x;
    float* p1 = &o1.x;
#pragma unroll
    for (int j = 0; j < 4; j++) {
      unsigned e = 4u * g + j;
      uint32_t wa = tf_xor(ka0, ka1, ka2, a_i1, a_i2, a_i3, a_i4, a_i5, tka + e, one);
      uint32_t wb = tf_xor(kb0, kb1, kb2, b_i1, b_i2, b_i3, b_i4, b_i5, tkb + e, one);
      float z0, z1;
      erfinv_pair(wa, wb, z0, z1);
      float xv0 = __ldg(xb + ((u0 + e) & 4095u));
      float xv1 = __ldg(xb + ((u1 + e) & 4095u));
      p0[j] = (xv0 + z0 * sd) * ms0;
      p1[j] = (xv1 + z1 * sd) * ms1;
    }
    *reinterpret_cast<float4*>(out + base + s0 + 4u * g)        = o0;
    *reinterpret_cast<float4*>(out + NTOT + base + s0 + 4u * g) = o1;
  }
}

// ---------------- host-side Threefry for constant key derivation ----------------
static inline uint32_t h_rotl(uint32_t x, int r) { return (x << r) | (x >> (32 - r)); }
static void h_tf(uint32_t k0, uint32_t k1, uint32_t x0, uint32_t x1,
                 uint32_t* o0, uint32_t* o1) {
  uint32_t k2 = k0 ^ k1 ^ 0x1BD11BDAu;
  x0 += k0; x1 += k1;
#define HR(r) { x0 += x1; x1 = h_rotl(x1, r); x1 ^= x0; }
  HR(13) HR(15) HR(26) HR(6)  x0 += k1; x1 += k2 + 1u;
  HR(17) HR(29) HR(16) HR(24) x0 += k2; x1 += k0 + 2u;
  HR(13) HR(15) HR(26) HR(6)  x0 += k0; x1 += k1 + 3u;
  HR(17) HR(29) HR(16) HR(24) x0 += k1; x1 += k2 + 4u;
  HR(13) HR(15) HR(26) HR(6)  x0 += k2; x1 += k0 + 5u;
#undef HR
  *o0 = x0; *o1 = x1;
}

extern "C" void kernel_launch(void* const* d_in, const int* in_sizes, int n_in,
                              void* d_out, int out_size) {
  const float* x = (const float*)d_in[0];
  float* out = (float*)d_out;

  uint32_t vk[2][2];
  h_tf(0u, 42u, 0u, 1u, &vk[0][0], &vk[0][1]);
  h_tf(0u, 42u, 0u, 2u, &vk[1][0], &vk[1][1]);

  uint4 kshA, kshB, knoise, kmask, kscale;
  for (int v = 0; v < 2; v++) {
    uint32_t kj[4][2];
    for (uint32_t j = 0; j < 4; j++)
      h_tf(vk[v][0], vk[v][1], 0u, j, &kj[j][0], &kj[j][1]);
    uint32_t s1[2], s2[2];
    h_tf(kj[0][0], kj[0][1], 0u, 0u, &s1[0], &s1[1]);
    h_tf(kj[0][0], kj[0][1], 0u, 1u, &s2[0], &s2[1]);
    if (v == 0) {
      kshA.x = s1[0]; kshA.y = s1[1]; kshA.z = s2[0]; kshA.w = s2[1];
      knoise.x = kj[1][0]; knoise.y = kj[1][1];
      kmask.x  = kj[2][0]; kmask.y  = kj[2][1];
      kscale.x = kj[3][0]; kscale.y = kj[3][1];
    } else {
      kshB.x = s1[0]; kshB.y = s1[1]; kshB.z = s2[0]; kshB.w = s2[1];
      knoise.z = kj[1][0]; knoise.w = kj[1][1];
      kmask.z  = kj[2][0]; kmask.w  = kj[2][1];
      kscale.z = kj[3][0]; kscale.w = kj[3][1];
    }
  }

  prep_kernel<<<NROW, 128>>>(x, kshA, kshB, kmask, kscale);
  main_kernel<<<(unsigned)(NTOT / 8 / 256), 256>>>(x, out, knoise, 1u);
}

// round 14
// speedup vs baseline: 1.1413x; 1.0060x over previous
#include <cuda_runtime.h>
#include <cstdint>

// ---------------- constants ----------------
#define B_   128
#define C_   64
#define S_   4096
#define NROW (B_*C_)            // 8192
#define NTOT ((size_t)B_*C_*S_) // 33554432

// ---------------- scratch (no allocation allowed) ----------------
__device__ float g_sd[NROW];        // sqrt2 * 0.1 * per-row std (shared by views)
__device__ int   g_shift[2*B_];
__device__ float g_scale[2*B_];
__device__ float g_mask[2*NROW];

// ---------------- Threefry-2x32-20 (JAX-exact) ----------------
#define TF_R(x0,x1,r) { x0 += x1; x1 = __funnelshift_l(x1,x1,r); x1 ^= x0; }

// plain version (prep kernel, low volume, bit-exact)
__device__ __forceinline__ void tf_block0(uint32_t k0, uint32_t k1,
                                          uint32_t c1,
                                          uint32_t &o0, uint32_t &o1) {
  uint32_t k2 = k0 ^ k1 ^ 0x1BD11BDAu;
  uint32_t x0 = k0, x1 = c1 + k1;
  TF_R(x0,x1,13) TF_R(x0,x1,15) TF_R(x0,x1,26) TF_R(x0,x1,6)
  x0 += k1; x1 += k2 + 1u;
  TF_R(x0,x1,17) TF_R(x0,x1,29) TF_R(x0,x1,16) TF_R(x0,x1,24)
  x0 += k2; x1 += k0 + 2u;
  TF_R(x0,x1,13) TF_R(x0,x1,15) TF_R(x0,x1,26) TF_R(x0,x1,6)
  x0 += k0; x1 += k1 + 3u;
  TF_R(x0,x1,17) TF_R(x0,x1,29) TF_R(x0,x1,16) TF_R(x0,x1,24)
  x0 += k1; x1 += k2 + 4u;
  TF_R(x0,x1,13) TF_R(x0,x1,15) TF_R(x0,x1,26) TF_R(x0,x1,6)
  o0 = x0 + k2; o1 = x1 + k0 + 5u;
}

__device__ __forceinline__ uint32_t xbits(uint32_t k0, uint32_t k1, uint32_t i) {
  uint32_t o0, o1;
  tf_block0(k0, k1, i, o0, o1);
  return o0 ^ o1;
}

// ---- hot-path block: EVERY add as IMAD (fma pipe) via runtime `one`.
// alu keeps only the structural SHF+LOP3 floor. Key-derived constants come
// from kernel params (UR path on sm_103a) — zero GPR cost.
// Output: (x0^x1)|0x200 — forces the uniform's low mantissa bit so x != -1.
#define MAD1(d,a) asm("mad.lo.u32 %0, %1, %2, %0;" : "+r"(d) : "r"(a), "r"(one))
#define TF_RM(r)  { MAD1(x0,x1); x1 = __funnelshift_l(x1,x1,r); x1 ^= x0; }

// kk = (k0, k1, k2, i1); ii = (i2, i3, i4, i5)
__device__ __forceinline__ uint32_t tf_xor(const uint4 kk, const uint4 ii,
                                           uint32_t x1init, uint32_t one) {
  uint32_t x0 = kk.x, x1 = x1init;
  TF_RM(13) TF_RM(15) TF_RM(26) TF_RM(6)
  MAD1(x0, kk.y); MAD1(x1, kk.w);
  TF_RM(17) TF_RM(29) TF_RM(16) TF_RM(24)
  MAD1(x0, kk.z); MAD1(x1, ii.x);
  TF_RM(13) TF_RM(15) TF_RM(26) TF_RM(6)
  MAD1(x0, kk.x); MAD1(x1, ii.y);
  TF_RM(17) TF_RM(29) TF_RM(16) TF_RM(24)
  MAD1(x0, kk.y); MAD1(x1, ii.z);
  TF_RM(13) TF_RM(15) TF_RM(26) TF_RM(6)
  MAD1(x0, kk.z); MAD1(x1, ii.w);
  return (x0 ^ x1) | 0x200u;
}

// bits -> float in [0,1): JAX _uniform exact (prep path)
__device__ __forceinline__ float u01(uint32_t b) {
  return __uint_as_float((b >> 9) | 0x3F800000u) - 1.0f;
}

// ---------------- packed f32x2 helpers ----------------
__device__ __forceinline__ uint64_t pk2(float lo, float hi) {
  uint64_t r; asm("mov.b64 %0, {%1, %2};" : "=l"(r) : "f"(lo), "f"(hi)); return r;
}
#define FMA2(d,a,b,c) asm("fma.rn.f32x2 %0, %1, %2, %3;" : "=l"(d) : "l"(a), "l"(b), "l"(c))
#define MUL2(d,a,b)   asm("mul.rn.f32x2 %0, %1, %2;"     : "=l"(d) : "l"(a), "l"(b))

// rare tail branch (w >= 5; ~0.34% of draws)
__device__ __forceinline__ float erfinv_tail(float v) {
  float w = -0.69314718f * v;
  float t = sqrtf(w) - 3.0f;
  float p = 0.00573950773f;
  p = fmaf(p, t, -0.0076224613f);
  p = fmaf(p, t, 0.00943887047f);
  p = fmaf(p, t, 1.00167406f);
  p = fmaf(p, t, 2.83297682f);
  return p;
}

// erfinv for the two views of one element, central poly packed f32x2.
// Lane-wise IEEE-identical to the scalar version (validated: rel_err match).
__device__ __forceinline__ void erfinv_pair(uint32_t ba, uint32_t bb,
                                            float &za, float &zb) {
  uint32_t ia, ib;
  asm("mad.hi.u32 %0, %1, 0x800000U, 0x40000000U;" : "=r"(ia) : "r"(ba));
  asm("mad.hi.u32 %0, %1, 0x800000U, 0x40000000U;" : "=r"(ib) : "r"(bb));
  float xa = __uint_as_float(ia) - 3.0f;        // in (-1,1), never +-1
  float xb = __uint_as_float(ib) - 3.0f;
  float va = __log2f(fmaf(-xa, xa, 1.0f));      // lg2(1 - x^2) < 0
  float vb = __log2f(fmaf(-xb, xb, 1.0f));
  uint64_t vv = pk2(va, vb);
  uint64_t xx = pk2(xa, xb);
  uint64_t pp = pk2(5.0456135e-5f, 5.0456135e-5f);
  const uint64_t c1 = pk2(1.1454495e-3f, 1.1454495e-3f);
  const uint64_t c2 = pk2(6.4486591e-3f, 6.4486591e-3f);
  const uint64_t c3 = pk2(-0.15967367f, -0.15967367f);
  const uint64_t c4 = pk2(0.88682485f, 0.88682485f);
  FMA2(pp, pp, vv, c1);
  FMA2(pp, pp, vv, c2);
  FMA2(pp, pp, vv, c3);
  FMA2(pp, pp, vv, c4);
  uint64_t zz;
  MUL2(zz, pp, xx);
  asm("mov.b64 {%0, %1}, %2;" : "=f"(za), "=f"(zb) : "l"(zz));
  if (va <= -7.2134752f) za = erfinv_tail(va) * xa;   // w >= 5 tail fixup
  if (vb <= -7.2134752f) zb = erfinv_tail(vb) * xb;
}

// ---------------- fused prep: per-row std + shifts/masks/scales ----------------
__global__ void prep_kernel(const float* __restrict__ x,
                            uint4 kshA, uint4 kshB, uint4 kmask, uint4 kscale) {
  unsigned gt = blockIdx.x * blockDim.x + threadIdx.x;
  if (gt < 2u * 8448u) {
    int v = (gt >= 8448u);
    unsigned i = gt - (unsigned)v * 8448u;
    if (i < 8192u) {
      uint32_t k0 = v ? kmask.z : kmask.x, k1 = v ? kmask.w : kmask.y;
      g_mask[v * NROW + i] = (u01(xbits(k0, k1, i)) > 0.1f) ? 1.0f : 0.0f;
    } else if (i < 8320u) {
      // randint: k1,k2 = split(k_shift); higher from k1, lower from k2; 68 = 2^32 % 101
      unsigned b = i - 8192u;
      uint4 ks = v ? kshB : kshA;
      uint32_t hb = xbits(ks.x, ks.y, b);
      uint32_t lb = xbits(ks.z, ks.w, b);
      uint32_t off = ((hb % 101u) * 68u + (lb % 101u)) % 101u;
      g_shift[v * B_ + b] = -50 + (int)off;
    } else {
      unsigned j = i - 8320u;
      uint32_t k0 = v ? kscale.z : kscale.x, k1 = v ? kscale.w : kscale.y;
      float u = u01(xbits(k0, k1, j));
      const float span = 1.2f - 0.8f;
      g_scale[v * B_ + j] = fmaxf(0.8f, __fadd_rn(__fmul_rn(u, span), 0.8f));
    }
  }

  int row = blockIdx.x;
  const float4* xr = reinterpret_cast<const float4*>(x + ((size_t)row << 12));
  float s = 0.0f, q = 0.0f;
#pragma unroll
  for (int i = 0; i < 8; i++) {
    float4 v = xr[threadIdx.x + (i << 7)];
    s += (v.x + v.y) + (v.z + v.w);
    q += (v.x * v.x + v.y * v.y) + (v.z * v.z + v.w * v.w);
  }
#pragma unroll
  for (int o = 16; o; o >>= 1) {
    s += __shfl_down_sync(0xFFFFFFFFu, s, o);
    q += __shfl_down_sync(0xFFFFFFFFu, q, o);
  }
  __shared__ float ss[4], qq[4];
  int w = threadIdx.x >> 5;
  if ((threadIdx.x & 31) == 0) { ss[w] = s; qq[w] = q; }
  __syncthreads();
  if (threadIdx.x == 0) {
    s = ss[0] + ss[1] + ss[2] + ss[3];
    q = qq[0] + qq[1] + qq[2] + qq[3];
    float mean = s * (1.0f / 4096.0f);
    float var = (q - 4096.0f * mean * mean) * (1.0f / 4095.0f);
    // fold 0.1 (NOISE_STD) and sqrt(2) (from normal) into one factor
    g_sd[row] = 0.141421356237f * sqrtf(fmaxf(var, 0.0f));
  }
}

// ---------------- main: 8 consecutive elements per thread, both views ----------------
// kA = (ka0, ka1, ka2, ka2+1); iA = (ka0+2, ka1+3, ka2+4, ka0+5); same for B.
__global__ void __launch_bounds__(256) main_kernel(const float* __restrict__ x,
                                                   float* __restrict__ out,
                                                   uint4 kA, uint4 iA,
                                                   uint4 kB, uint4 iB,
                                                   uint32_t one) {
  unsigned t0 = (blockIdx.x * blockDim.x + threadIdx.x) * 8u;  // s%8==0
  int b = t0 >> 18;
  int s0 = t0 & 4095;
  int row = t0 >> 12;
  size_t base = (size_t)row << 12;
  float sd = g_sd[row];
  unsigned u0 = (unsigned)((s0 - g_shift[b]) & 4095);        // rolled start, view 0
  unsigned u1 = (unsigned)((s0 - g_shift[B_ + b]) & 4095);   // rolled start, view 1
  float ms0 = g_mask[row]        * g_scale[b];
  float ms1 = g_mask[NROW + row] * g_scale[B_ + b];
  const float* xb = x + base;

  uint32_t tka = t0 + kA.y;   // counter + k1, view 0
  uint32_t tkb = t0 + kB.y;   // counter + k1, view 1

#pragma unroll
  for (int g = 0; g < 2; g++) {                 // two float4 groups
    float4 o0, o1;
    float* p0 = &o0.x;
    float* p1 = &o1.x;
#pragma unroll
    for (int j = 0; j < 4; j++) {
      unsigned e = 4u * g + j;
      uint32_t wa = tf_xor(kA, iA, tka + e, one);
      uint32_t wb = tf_xor(kB, iB, tkb + e, one);
      float z0, z1;
      erfinv_pair(wa, wb, z0, z1);
      float xv0 = __ldg(xb + ((u0 + e) & 4095u));
      float xv1 = __ldg(xb + ((u1 + e) & 4095u));
      p0[j] = (xv0 + z0 * sd) * ms0;
      p1[j] = (xv1 + z1 * sd) * ms1;
    }
    *reinterpret_cast<float4*>(out + base + s0 + 4u * g)        = o0;
    *reinterpret_cast<float4*>(out + NTOT + base + s0 + 4u * g) = o1;
  }
}

// ---------------- host-side Threefry for constant key derivation ----------------
static inline uint32_t h_rotl(uint32_t x, int r) { return (x << r) | (x >> (32 - r)); }
static void h_tf(uint32_t k0, uint32_t k1, uint32_t x0, uint32_t x1,
                 uint32_t* o0, uint32_t* o1) {
  uint32_t k2 = k0 ^ k1 ^ 0x1BD11BDAu;
  x0 += k0; x1 += k1;
#define HR(r) { x0 += x1; x1 = h_rotl(x1, r); x1 ^= x0; }
  HR(13) HR(15) HR(26) HR(6)  x0 += k1; x1 += k2 + 1u;
  HR(17) HR(29) HR(16) HR(24) x0 += k2; x1 += k0 + 2u;
  HR(13) HR(15) HR(26) HR(6)  x0 += k0; x1 += k1 + 3u;
  HR(17) HR(29) HR(16) HR(24) x0 += k1; x1 += k2 + 4u;
  HR(13) HR(15) HR(26) HR(6)  x0 += k2; x1 += k0 + 5u;
#undef HR
  *o0 = x0; *o1 = x1;
}

extern "C" void kernel_launch(void* const* d_in, const int* in_sizes, int n_in,
                              void* d_out, int out_size) {
  const float* x = (const float*)d_in[0];
  float* out = (float*)d_out;

  uint32_t vk[2][2];
  h_tf(0u, 42u, 0u, 1u, &vk[0][0], &vk[0][1]);
  h_tf(0u, 42u, 0u, 2u, &vk[1][0], &vk[1][1]);

  uint4 kshA, kshB, kmask, kscale;
  uint32_t kn[2][2];   // noise keys per view
  for (int v = 0; v < 2; v++) {
    uint32_t kj[4][2];
    for (uint32_t j = 0; j < 4; j++)
      h_tf(vk[v][0], vk[v][1], 0u, j, &kj[j][0], &kj[j][1]);
    uint32_t s1[2], s2[2];
    h_tf(kj[0][0], kj[0][1], 0u, 0u, &s1[0], &s1[1]);
    h_tf(kj[0][0], kj[0][1], 0u, 1u, &s2[0], &s2[1]);
    kn[v][0] = kj[1][0]; kn[v][1] = kj[1][1];
    if (v == 0) {
      kshA.x = s1[0]; kshA.y = s1[1]; kshA.z = s2[0]; kshA.w = s2[1];
      kmask.x  = kj[2][0]; kmask.y  = kj[2][1];
      kscale.x = kj[3][0]; kscale.y = kj[3][1];
    } else {
      kshB.x = s1[0]; kshB.y = s1[1]; kshB.z = s2[0]; kshB.w = s2[1];
      kmask.z  = kj[2][0]; kmask.w  = kj[2][1];
      kscale.z = kj[3][0]; kscale.w = kj[3][1];
    }
  }

  // derived threefry constants, host-side (live in param/constant space)
  uint4 kkv[2], iiv[2];
  for (int v = 0; v < 2; v++) {
    uint32_t k0 = kn[v][0], k1 = kn[v][1];
    uint32_t k2 = k0 ^ k1 ^ 0x1BD11BDAu;
    kkv[v].x = k0;      kkv[v].y = k1;      kkv[v].z = k2;      kkv[v].w = k2 + 1u;
    iiv[v].x = k0 + 2u; iiv[v].y = k1 + 3u; iiv[v].z = k2 + 4u; iiv[v].w = k0 + 5u;
  }

  prep_kernel<<<NROW, 128>>>(x, kshA, kshB, kmask, kscale);
  main_kernel<<<(unsigned)(NTOT / 8 / 256), 256>>>(x, out, kkv[0], iiv[0],
                                                   kkv[1], iiv[1], 1u);
}